// round 1
// baseline (speedup 1.0000x reference)
#include <cuda_runtime.h>
#include <cstdint>

// Problem constants
#define NB   8      // batch
#define CH   16     // in channels (= heads)
#define LEN  1024   // sequence length
#define DD   7      // per-head dim
#define SZ   112    // CH*DD
#define HH   16     // out heads
#define NH   (NB*HH)      // 128 (n,h) pairs
#define DPAD 8            // padded head dim

// Scratch: padded q,k,v  [NH][LEN][DPAD]
__device__ float g_q[NH * LEN * DPAD];
__device__ float g_k[NH * LEN * DPAD];
__device__ float g_v[NH * LEN * DPAD];

// ---------------------------------------------------------------------------
// Kernel 1: QKV projection.  y[row][j] = sum_c xf[row][c]*W[j][c] + b[j]
// rows = N*L = 8192, xf[row][c] = x[n][c/7][l][c%7], row = n*1024 + l
// Block: 224 threads = 28 (j-groups of 4) x 8 (row-groups of 8). 64 rows/blk.
// blockIdx.y selects which of Wq/Wk/Wv.
// ---------------------------------------------------------------------------
#define PROJ_ROWS 64
#define XS_PITCH  113
#define PROJ_SMEM ((SZ*SZ + PROJ_ROWS*XS_PITCH) * 4)

__global__ __launch_bounds__(224, 4)
void proj_kernel(const float* __restrict__ x,
                 const float* __restrict__ Wq, const float* __restrict__ bq,
                 const float* __restrict__ Wk, const float* __restrict__ bk,
                 const float* __restrict__ Wv, const float* __restrict__ bv)
{
    extern __shared__ float sm[];
    float* Wt = sm;                 // [112][112], Wt[k*112+j] = W[j][k]
    float* xs = sm + SZ * SZ;       // [64][113]

    const int m = blockIdx.y;
    const float* W = (m == 0) ? Wq : (m == 1) ? Wk : Wv;
    const float* b = (m == 0) ? bq : (m == 1) ? bk : bv;
    float* dst     = (m == 0) ? g_q : (m == 1) ? g_k : g_v;

    const int t = threadIdx.x;   // 0..223

    // Stage W transposed into smem
    for (int i = t; i < SZ * SZ; i += 224) {
        int j = i / SZ, k = i - j * SZ;
        Wt[k * SZ + j] = W[i];
    }
    // Stage 64 rows of xf
    const int base = blockIdx.x * PROJ_ROWS;
    for (int i = t; i < PROJ_ROWS * SZ; i += 224) {
        int r = i / SZ, c = i - r * SZ;
        int row = base + r;
        int n = row >> 10, l = row & 1023;
        xs[r * XS_PITCH + c] = x[((n * CH + c / DD) * LEN + l) * DD + (c % DD)];
    }
    __syncthreads();

    const int jt = t % 28;          // column group
    const int rt = t / 28;          // row group
    const int j0 = jt * 4;
    const int r0 = rt * 8;

    float acc[8][4];
    #pragma unroll
    for (int rr = 0; rr < 8; rr++) {
        #pragma unroll
        for (int jj = 0; jj < 4; jj++) acc[rr][jj] = b[j0 + jj];
    }

    #pragma unroll 4
    for (int k = 0; k < SZ; k++) {
        const float4 wv = *reinterpret_cast<const float4*>(Wt + k * SZ + j0);
        #pragma unroll
        for (int rr = 0; rr < 8; rr++) {
            const float xv = xs[(r0 + rr) * XS_PITCH + k];
            acc[rr][0] = fmaf(xv, wv.x, acc[rr][0]);
            acc[rr][1] = fmaf(xv, wv.y, acc[rr][1]);
            acc[rr][2] = fmaf(xv, wv.z, acc[rr][2]);
            acc[rr][3] = fmaf(xv, wv.w, acc[rr][3]);
        }
    }

    // Write to padded [n*H + h][l][dpad] scratch
    #pragma unroll
    for (int rr = 0; rr < 8; rr++) {
        int row = base + r0 + rr;
        int n = row >> 10, l = row & 1023;
        #pragma unroll
        for (int jj = 0; jj < 4; jj++) {
            int j = j0 + jj;
            int h = j / DD, dd = j - h * DD;
            dst[((n * HH + h) * LEN + l) * DPAD + dd] = acc[rr][jj];
        }
    }
}

// ---------------------------------------------------------------------------
// Kernel 2: attention. One CTA per (nh, 128-query slice). K,V in smem.
// Single-pass softmax: scores are tiny (|s| << 1) so exp without max-subtract
// is numerically exact in fp32 and identical to the reference after /sum.
// ---------------------------------------------------------------------------
#define QSPLIT 8
#define ATHREADS 128
#define ATTN_SMEM (2 * LEN * DPAD * 4)   // 65536

__global__ __launch_bounds__(ATHREADS, 3)
void attn_kernel(float* __restrict__ out)
{
    extern __shared__ float sm[];
    float* ks = sm;                // [1024][8]
    float* vs = sm + LEN * DPAD;   // [1024][8]

    const int nh = blockIdx.x;

    // Stage K,V (float4, fully coalesced)
    {
        const float4* ksrc = reinterpret_cast<const float4*>(g_k + nh * LEN * DPAD);
        const float4* vsrc = reinterpret_cast<const float4*>(g_v + nh * LEN * DPAD);
        float4* kd = reinterpret_cast<float4*>(ks);
        float4* vd = reinterpret_cast<float4*>(vs);
        for (int i = threadIdx.x; i < LEN * DPAD / 4; i += ATHREADS) {
            kd[i] = ksrc[i];
            vd[i] = vsrc[i];
        }
    }
    __syncthreads();

    const int q = blockIdx.y * ATHREADS + threadIdx.x;
    const float* qp = g_q + (nh * LEN + q) * DPAD;

    // fold softmax scale (1/sqrt(L)=1/32) and log2(e) into q
    const float SC = 1.4426950408889634f / 32.0f;
    const float q0 = qp[0] * SC, q1 = qp[1] * SC, q2 = qp[2] * SC,
                q3 = qp[3] * SC, q4 = qp[4] * SC, q5 = qp[5] * SC,
                q6 = qp[6] * SC;

    float ssum = 0.0f;
    float a0 = 0.f, a1 = 0.f, a2 = 0.f, a3 = 0.f, a4 = 0.f, a5 = 0.f, a6 = 0.f;

    #pragma unroll 4
    for (int j = 0; j < LEN; j++) {
        const float* kj = ks + j * DPAD;
        float s = q0 * kj[0];
        s = fmaf(q1, kj[1], s);
        s = fmaf(q2, kj[2], s);
        s = fmaf(q3, kj[3], s);
        s = fmaf(q4, kj[4], s);
        s = fmaf(q5, kj[5], s);
        s = fmaf(q6, kj[6], s);
        float e;
        asm("ex2.approx.ftz.f32 %0, %1;" : "=f"(e) : "f"(s));
        ssum += e;
        const float* vj = vs + j * DPAD;
        a0 = fmaf(e, vj[0], a0);
        a1 = fmaf(e, vj[1], a1);
        a2 = fmaf(e, vj[2], a2);
        a3 = fmaf(e, vj[3], a3);
        a4 = fmaf(e, vj[4], a4);
        a5 = fmaf(e, vj[5], a5);
        a6 = fmaf(e, vj[6], a6);
    }

    const float inv = 1.0f / ssum;
    float* op = out + (nh * LEN + q) * DD;
    op[0] = a0 * inv; op[1] = a1 * inv; op[2] = a2 * inv; op[3] = a3 * inv;
    op[4] = a4 * inv; op[5] = a5 * inv; op[6] = a6 * inv;
}

// ---------------------------------------------------------------------------
extern "C" void kernel_launch(void* const* d_in, const int* in_sizes, int n_in,
                              void* d_out, int out_size)
{
    const float* x  = (const float*)d_in[0];
    const float* Wq = (const float*)d_in[1];
    const float* bq = (const float*)d_in[2];
    const float* Wk = (const float*)d_in[3];
    const float* bk = (const float*)d_in[4];
    const float* Wv = (const float*)d_in[5];
    const float* bv = (const float*)d_in[6];
    float* out = (float*)d_out;

    cudaFuncSetAttribute(proj_kernel, cudaFuncAttributeMaxDynamicSharedMemorySize, PROJ_SMEM);
    cudaFuncSetAttribute(attn_kernel, cudaFuncAttributeMaxDynamicSharedMemorySize, ATTN_SMEM);

    dim3 pgrid((NB * LEN) / PROJ_ROWS, 3);   // 128 x 3
    proj_kernel<<<pgrid, 224, PROJ_SMEM>>>(x, Wq, bq, Wk, bk, Wv, bv);

    dim3 agrid(NH, QSPLIT);                  // 128 x 8
    attn_kernel<<<agrid, ATHREADS, ATTN_SMEM>>>(out);
}

// round 2
// speedup vs baseline: 1.1699x; 1.1699x over previous
#include <cuda_runtime.h>
#include <cstdint>

#define NB   8
#define CH   16
#define LEN  1024
#define DD   7
#define SZ   112
#define HH   16
#define NH   (NB*HH)      // 128
#define DPAD 8

typedef unsigned long long u64;

// Scratch
__device__ float g_q[NH * LEN * DPAD];
__device__ float g_k[NH * LEN * DPAD];
__device__ float g_v[NH * LEN * DPAD];
__device__ float g_part[2 * NH * LEN * DPAD];   // [chunk][nh][l][8] partials
__device__ u64   g_w2[3 * 56 * SZ];             // packed W: [m][k2][j] = {W[j][2k2], W[j][2k2+1]}

// ---- f32x2 helpers (sm_103a packed fp32: 2 FMAs per instruction) ----
__device__ __forceinline__ u64 pack2(float lo, float hi) {
    u64 r; asm("mov.b64 %0,{%1,%2};" : "=l"(r) : "f"(lo), "f"(hi)); return r;
}
__device__ __forceinline__ void unpack2(u64 v, float& lo, float& hi) {
    asm("mov.b64 {%0,%1},%2;" : "=f"(lo), "=f"(hi) : "l"(v));
}
__device__ __forceinline__ u64 fma2(u64 a, u64 b, u64 c) {
    u64 d; asm("fma.rn.f32x2 %0,%1,%2,%3;" : "=l"(d) : "l"(a), "l"(b), "l"(c)); return d;
}
__device__ __forceinline__ u64 mul2(u64 a, u64 b) {
    u64 d; asm("mul.rn.f32x2 %0,%1,%2;" : "=l"(d) : "l"(a), "l"(b)); return d;
}

// ---------------------------------------------------------------------------
// Kernel 0: pack W matrices into [k2][j] u64 table (k-pairs contiguous in W rows)
// ---------------------------------------------------------------------------
__global__ void prep_kernel(const float* __restrict__ Wq,
                            const float* __restrict__ Wk,
                            const float* __restrict__ Wv)
{
    int i = blockIdx.x * 256 + threadIdx.x;
    if (i >= 3 * 56 * SZ) return;
    int m   = i / (56 * SZ);
    int rem = i - m * 56 * SZ;
    int k2  = rem / SZ;
    int j   = rem - k2 * SZ;
    const float* W = (m == 0) ? Wq : (m == 1) ? Wk : Wv;
    // source elements W[j][2k2], W[j][2k2+1] are contiguous -> one u64 load
    g_w2[i] = *reinterpret_cast<const u64*>(W + j * SZ + 2 * k2);
}

// ---------------------------------------------------------------------------
// Kernel 1: QKV projection with k-packed f32x2 FMA.
// Block: 224 thr = 28 j-groups (4 j each) x 8 row-groups (4 rows each). 32 rows/blk.
// ---------------------------------------------------------------------------
#define PROJ_ROWS 32
#define PTHREADS  224
#define PROJ_SMEM (56 * SZ * 8 + PROJ_ROWS * SZ * 4)   // Wt2 (u64) + xs (float)

__global__ __launch_bounds__(PTHREADS, 3)
void proj_kernel(const float* __restrict__ x,
                 const float* __restrict__ bq,
                 const float* __restrict__ bk,
                 const float* __restrict__ bv)
{
    extern __shared__ char smraw[];
    u64*   Wt2 = reinterpret_cast<u64*>(smraw);          // [56][112]
    float* xs  = reinterpret_cast<float*>(smraw + 56 * SZ * 8);  // [32][112]

    const int m = blockIdx.y;
    const float* b = (m == 0) ? bq : (m == 1) ? bk : bv;
    float* dst     = (m == 0) ? g_q : (m == 1) ? g_k : g_v;

    const int t = threadIdx.x;

    // Stage packed W (coalesced u64 copy from global table)
    const u64* wsrc = g_w2 + m * 56 * SZ;
    #pragma unroll
    for (int i = 0; i < 28; i++) Wt2[i * PTHREADS + t] = wsrc[i * PTHREADS + t];

    // Stage 32 rows of xf (scalar gather from x)
    const int base = blockIdx.x * PROJ_ROWS;
    #pragma unroll
    for (int it = 0; it < 16; it++) {
        int i = it * PTHREADS + t;
        int r = i / SZ, c = i - r * SZ;
        int row = base + r;
        int n = row >> 10, l = row & 1023;
        xs[r * SZ + c] = x[((n * CH + c / DD) * LEN + l) * DD + (c % DD)];
    }
    __syncthreads();

    const int jt = t % 28, rt = t / 28;
    const int j0 = jt * 4, r0 = rt * 4;

    u64 acc[4][4];
    #pragma unroll
    for (int rr = 0; rr < 4; rr++)
        #pragma unroll
        for (int jj = 0; jj < 4; jj++) acc[rr][jj] = 0ull;

    #pragma unroll 4
    for (int k2 = 0; k2 < 56; k2++) {
        ulonglong2 wA = *reinterpret_cast<const ulonglong2*>(Wt2 + k2 * SZ + j0);
        ulonglong2 wB = *reinterpret_cast<const ulonglong2*>(Wt2 + k2 * SZ + j0 + 2);
        #pragma unroll
        for (int rr = 0; rr < 4; rr++) {
            u64 xv = *reinterpret_cast<const u64*>(xs + (r0 + rr) * SZ + 2 * k2);
            acc[rr][0] = fma2(xv, wA.x, acc[rr][0]);
            acc[rr][1] = fma2(xv, wA.y, acc[rr][1]);
            acc[rr][2] = fma2(xv, wB.x, acc[rr][2]);
            acc[rr][3] = fma2(xv, wB.y, acc[rr][3]);
        }
    }

    #pragma unroll
    for (int rr = 0; rr < 4; rr++) {
        int row = base + r0 + rr;
        int n = row >> 10, l = row & 1023;
        #pragma unroll
        for (int jj = 0; jj < 4; jj++) {
            int j = j0 + jj;
            float lo, hi; unpack2(acc[rr][jj], lo, hi);
            float y = lo + hi + b[j];
            int h = j / DD, dd = j - h * DD;
            dst[((n * HH + h) * LEN + l) * DPAD + dd] = y;
        }
    }
}

// ---------------------------------------------------------------------------
// Kernel 2: attention partial pass. Grid (NH, 8 q-slices, 2 k-chunks).
// Each CTA: 128 queries x 512 keys, K/V chunk in 32KB smem.
// Packed f32x2: QK dot = 4 fma2, PV+ssum = 4 fma2 (V lane 7 = 1.0).
// ---------------------------------------------------------------------------
#define ATHREADS 128
#define KCH 512
#define ATTN_SMEM (2 * KCH * DPAD * 4)   // 32768

__global__ __launch_bounds__(ATHREADS, 7)
void attn_kernel()
{
    extern __shared__ float sm[];
    float* ks = sm;                 // [512][8]
    float* vs = sm + KCH * DPAD;

    const int nh = blockIdx.x;
    const int ch = blockIdx.z;
    const int t  = threadIdx.x;

    {   // stage K/V chunk (coalesced float4)
        const float4* ksrc = reinterpret_cast<const float4*>(g_k + (nh * LEN + ch * KCH) * DPAD);
        const float4* vsrc = reinterpret_cast<const float4*>(g_v + (nh * LEN + ch * KCH) * DPAD);
        float4* kd = reinterpret_cast<float4*>(ks);
        float4* vd = reinterpret_cast<float4*>(vs);
        #pragma unroll
        for (int i = 0; i < KCH * DPAD / 4 / ATHREADS; i++) {
            kd[i * ATHREADS + t] = ksrc[i * ATHREADS + t];
            vd[i * ATHREADS + t] = vsrc[i * ATHREADS + t];
        }
    }
    __syncthreads();   // loads done before pad fix (pad slots overwritten below)
    #pragma unroll
    for (int j = t; j < KCH; j += ATHREADS) {
        ks[j * DPAD + 7] = 0.0f;    // kill garbage in pad lane (could be NaN)
        vs[j * DPAD + 7] = 1.0f;    // ssum rides in accumulator hi lane
    }
    __syncthreads();

    const int q = blockIdx.y * ATHREADS + t;
    const float* qp = g_q + (nh * LEN + q) * DPAD;

    const float SC = 1.4426950408889634f / 32.0f;   // log2(e)/sqrt(L)
    const u64 q01 = pack2(qp[0] * SC, qp[1] * SC);
    const u64 q23 = pack2(qp[2] * SC, qp[3] * SC);
    const u64 q45 = pack2(qp[4] * SC, qp[5] * SC);
    const u64 q67 = pack2(qp[6] * SC, 0.0f);

    u64 a01 = 0ull, a23 = 0ull, a45 = 0ull, a67 = 0ull;

    #pragma unroll 4
    for (int j = 0; j < KCH; j++) {
        const ulonglong2 kA = *reinterpret_cast<const ulonglong2*>(ks + j * DPAD);
        const ulonglong2 kB = *reinterpret_cast<const ulonglong2*>(ks + j * DPAD + 4);
        u64 s2 = mul2(q01, kA.x);
        s2 = fma2(q23, kA.y, s2);
        s2 = fma2(q45, kB.x, s2);
        s2 = fma2(q67, kB.y, s2);
        float lo, hi; unpack2(s2, lo, hi);
        float s = lo + hi;
        float e; asm("ex2.approx.ftz.f32 %0,%1;" : "=f"(e) : "f"(s));
        const u64 e2 = pack2(e, e);
        const ulonglong2 vA = *reinterpret_cast<const ulonglong2*>(vs + j * DPAD);
        const ulonglong2 vB = *reinterpret_cast<const ulonglong2*>(vs + j * DPAD + 4);
        a01 = fma2(e2, vA.x, a01);
        a23 = fma2(e2, vA.y, a23);
        a45 = fma2(e2, vB.x, a45);
        a67 = fma2(e2, vB.y, a67);   // hi lane accumulates ssum (v=1.0)
    }

    u64* pp = reinterpret_cast<u64*>(g_part) + (((size_t)ch * NH + nh) * LEN + q) * 4;
    ulonglong2 o0; o0.x = a01; o0.y = a23;
    ulonglong2 o1; o1.x = a45; o1.y = a67;
    *reinterpret_cast<ulonglong2*>(pp)     = o0;
    *reinterpret_cast<ulonglong2*>(pp + 2) = o1;
}

// ---------------------------------------------------------------------------
// Kernel 3: combine the two K-chunk partials and normalize.
// ---------------------------------------------------------------------------
__global__ void combine_kernel(float* __restrict__ out)
{
    int idx = blockIdx.x * 256 + threadIdx.x;      // over NH*LEN = 131072
    const float4* p0 = reinterpret_cast<const float4*>(g_part + (size_t)idx * 8);
    const float4* p1 = reinterpret_cast<const float4*>(g_part + (size_t)NH * LEN * 8 + (size_t)idx * 8);
    float4 A = p0[0], B = p0[1];
    float4 C = p1[0], D = p1[1];
    float inv = 1.0f / (B.w + D.w);
    float* op = out + (size_t)idx * DD;
    op[0] = (A.x + C.x) * inv;
    op[1] = (A.y + C.y) * inv;
    op[2] = (A.z + C.z) * inv;
    op[3] = (A.w + C.w) * inv;
    op[4] = (B.x + D.x) * inv;
    op[5] = (B.y + D.y) * inv;
    op[6] = (B.z + D.z) * inv;
}

// ---------------------------------------------------------------------------
extern "C" void kernel_launch(void* const* d_in, const int* in_sizes, int n_in,
                              void* d_out, int out_size)
{
    const float* x  = (const float*)d_in[0];
    const float* Wq = (const float*)d_in[1];
    const float* bq = (const float*)d_in[2];
    const float* Wk = (const float*)d_in[3];
    const float* bk = (const float*)d_in[4];
    const float* Wv = (const float*)d_in[5];
    const float* bv = (const float*)d_in[6];
    float* out = (float*)d_out;

    cudaFuncSetAttribute(proj_kernel, cudaFuncAttributeMaxDynamicSharedMemorySize, PROJ_SMEM);
    cudaFuncSetAttribute(attn_kernel, cudaFuncAttributeMaxDynamicSharedMemorySize, ATTN_SMEM);

    prep_kernel<<<(3 * 56 * SZ + 255) / 256, 256>>>(Wq, Wk, Wv);

    dim3 pgrid((NB * LEN) / PROJ_ROWS, 3);       // 256 x 3
    proj_kernel<<<pgrid, PTHREADS, PROJ_SMEM>>>(x, bq, bk, bv);

    dim3 agrid(NH, LEN / ATHREADS, 2);           // 128 x 8 x 2
    attn_kernel<<<agrid, ATHREADS, ATTN_SMEM>>>();

    combine_kernel<<<NH * LEN / 256, 256>>>(out);
}

// round 3
// speedup vs baseline: 1.3726x; 1.1732x over previous
#include <cuda_runtime.h>
#include <cstdint>

#define NB   8
#define CH   16
#define LEN  1024
#define DD   7
#define SZ   112
#define HH   16
#define NH   (NB*HH)      // 128
#define DPAD 8

typedef unsigned long long u64;

// Scratch
__device__ float g_q[NH * LEN * DPAD];
__device__ float g_k[NH * LEN * DPAD];
__device__ float g_v[NH * LEN * DPAD];
__device__ float g_part[2 * NH * LEN * DPAD];   // [chunk][nh][l][8]
__device__ u64   g_w2[3 * 56 * SZ];             // packed W: [m][k2][j]

// ---- f32x2 helpers ----
__device__ __forceinline__ u64 pack2(float lo, float hi) {
    u64 r; asm("mov.b64 %0,{%1,%2};" : "=l"(r) : "f"(lo), "f"(hi)); return r;
}
__device__ __forceinline__ void unpack2(u64 v, float& lo, float& hi) {
    asm("mov.b64 {%0,%1},%2;" : "=f"(lo), "=f"(hi) : "l"(v));
}
__device__ __forceinline__ u64 fma2(u64 a, u64 b, u64 c) {
    u64 d; asm("fma.rn.f32x2 %0,%1,%2,%3;" : "=l"(d) : "l"(a), "l"(b), "l"(c)); return d;
}
__device__ __forceinline__ u64 mul2(u64 a, u64 b) {
    u64 d; asm("mul.rn.f32x2 %0,%1,%2;" : "=l"(d) : "l"(a), "l"(b)); return d;
}

// ---------------------------------------------------------------------------
// Kernel 0: pack W into [k2][j] u64 table
// ---------------------------------------------------------------------------
__global__ void prep_kernel(const float* __restrict__ Wq,
                            const float* __restrict__ Wk,
                            const float* __restrict__ Wv)
{
    int i = blockIdx.x * 256 + threadIdx.x;
    if (i >= 3 * 56 * SZ) return;
    int m   = i / (56 * SZ);
    int rem = i - m * 56 * SZ;
    int k2  = rem / SZ;
    int j   = rem - k2 * SZ;
    const float* W = (m == 0) ? Wq : (m == 1) ? Wk : Wv;
    g_w2[i] = *reinterpret_cast<const u64*>(W + j * SZ + 2 * k2);
}

// ---------------------------------------------------------------------------
// Kernel 1: QKV projection (k-packed f32x2)
// ---------------------------------------------------------------------------
#define PROJ_ROWS 32
#define PTHREADS  224
#define PROJ_SMEM (56 * SZ * 8 + PROJ_ROWS * SZ * 4)

__global__ __launch_bounds__(PTHREADS, 3)
void proj_kernel(const float* __restrict__ x,
                 const float* __restrict__ bq,
                 const float* __restrict__ bk,
                 const float* __restrict__ bv)
{
    extern __shared__ char smraw[];
    u64*   Wt2 = reinterpret_cast<u64*>(smraw);                  // [56][112]
    float* xs  = reinterpret_cast<float*>(smraw + 56 * SZ * 8);  // [32][112]

    const int m = blockIdx.y;
    const float* b = (m == 0) ? bq : (m == 1) ? bk : bv;
    float* dst     = (m == 0) ? g_q : (m == 1) ? g_k : g_v;

    const int t = threadIdx.x;

    const u64* wsrc = g_w2 + m * 56 * SZ;
    #pragma unroll
    for (int i = 0; i < 28; i++) Wt2[i * PTHREADS + t] = wsrc[i * PTHREADS + t];

    const int base = blockIdx.x * PROJ_ROWS;
    #pragma unroll
    for (int it = 0; it < 16; it++) {
        int i = it * PTHREADS + t;
        int r = i / SZ, c = i - r * SZ;
        int row = base + r;
        int n = row >> 10, l = row & 1023;
        xs[r * SZ + c] = x[((n * CH + c / DD) * LEN + l) * DD + (c % DD)];
    }
    __syncthreads();

    const int jt = t % 28, rt = t / 28;
    const int j0 = jt * 4, r0 = rt * 4;

    u64 acc[4][4];
    #pragma unroll
    for (int rr = 0; rr < 4; rr++)
        #pragma unroll
        for (int jj = 0; jj < 4; jj++) acc[rr][jj] = 0ull;

    #pragma unroll 4
    for (int k2 = 0; k2 < 56; k2++) {
        ulonglong2 wA = *reinterpret_cast<const ulonglong2*>(Wt2 + k2 * SZ + j0);
        ulonglong2 wB = *reinterpret_cast<const ulonglong2*>(Wt2 + k2 * SZ + j0 + 2);
        #pragma unroll
        for (int rr = 0; rr < 4; rr++) {
            u64 xv = *reinterpret_cast<const u64*>(xs + (r0 + rr) * SZ + 2 * k2);
            acc[rr][0] = fma2(xv, wA.x, acc[rr][0]);
            acc[rr][1] = fma2(xv, wA.y, acc[rr][1]);
            acc[rr][2] = fma2(xv, wB.x, acc[rr][2]);
            acc[rr][3] = fma2(xv, wB.y, acc[rr][3]);
        }
    }

    #pragma unroll
    for (int rr = 0; rr < 4; rr++) {
        int row = base + r0 + rr;
        int n = row >> 10, l = row & 1023;
        #pragma unroll
        for (int jj = 0; jj < 4; jj++) {
            int j = j0 + jj;
            float lo, hi; unpack2(acc[rr][jj], lo, hi);
            float y = lo + hi + b[j];
            int h = j / DD, dd = j - h * DD;
            dst[((n * HH + h) * LEN + l) * DPAD + dd] = y;
        }
    }
}

// ---------------------------------------------------------------------------
// Kernel 2: attention partials. 64 threads x QBLOCK=4 queries, KCH=512 keys.
// K/V smem loads amortized over 4 query chains (crossbar relief).
// ---------------------------------------------------------------------------
#define ATHREADS 64
#define QBLOCK   4
#define QPC      (ATHREADS * QBLOCK)    // 256 queries per CTA
#define KCH      512
#define ATTN_SMEM (2 * KCH * DPAD * 4)  // 32768

__global__ __launch_bounds__(ATHREADS, 7)
void attn_kernel()
{
    extern __shared__ float sm[];
    float* ks = sm;
    float* vs = sm + KCH * DPAD;

    const int nh = blockIdx.x;
    const int ch = blockIdx.z;
    const int t  = threadIdx.x;

    {   // stage K/V chunk
        const float4* ksrc = reinterpret_cast<const float4*>(g_k + (nh * LEN + ch * KCH) * DPAD);
        const float4* vsrc = reinterpret_cast<const float4*>(g_v + (nh * LEN + ch * KCH) * DPAD);
        float4* kd = reinterpret_cast<float4*>(ks);
        float4* vd = reinterpret_cast<float4*>(vs);
        #pragma unroll
        for (int i = 0; i < KCH * DPAD / 4 / ATHREADS; i++) {
            kd[i * ATHREADS + t] = ksrc[i * ATHREADS + t];
            vd[i * ATHREADS + t] = vsrc[i * ATHREADS + t];
        }
    }
    __syncthreads();
    #pragma unroll
    for (int j = t; j < KCH; j += ATHREADS) {
        ks[j * DPAD + 7] = 0.0f;    // kill pad garbage
        vs[j * DPAD + 7] = 1.0f;    // ssum rides hi lane of acc[3]
    }
    __syncthreads();

    const int qbase = blockIdx.y * QPC + t;
    const float SC = 1.4426950408889634f / 32.0f;

    u64 qr[QBLOCK][4];
    u64 acc[QBLOCK][4];
    #pragma unroll
    for (int i = 0; i < QBLOCK; i++) {
        const float* qp = g_q + (nh * LEN + qbase + i * ATHREADS) * DPAD;
        qr[i][0] = pack2(qp[0] * SC, qp[1] * SC);
        qr[i][1] = pack2(qp[2] * SC, qp[3] * SC);
        qr[i][2] = pack2(qp[4] * SC, qp[5] * SC);
        qr[i][3] = pack2(qp[6] * SC, 0.0f);
        acc[i][0] = acc[i][1] = acc[i][2] = acc[i][3] = 0ull;
    }

    #pragma unroll 2
    for (int j = 0; j < KCH; j++) {
        const ulonglong2 kA = *reinterpret_cast<const ulonglong2*>(ks + j * DPAD);
        const ulonglong2 kB = *reinterpret_cast<const ulonglong2*>(ks + j * DPAD + 4);
        const ulonglong2 vA = *reinterpret_cast<const ulonglong2*>(vs + j * DPAD);
        const ulonglong2 vB = *reinterpret_cast<const ulonglong2*>(vs + j * DPAD + 4);
        #pragma unroll
        for (int i = 0; i < QBLOCK; i++) {
            u64 s2 = mul2(qr[i][0], kA.x);
            s2 = fma2(qr[i][1], kA.y, s2);
            s2 = fma2(qr[i][2], kB.x, s2);
            s2 = fma2(qr[i][3], kB.y, s2);
            float lo, hi; unpack2(s2, lo, hi);
            float s = lo + hi;
            float e; asm("ex2.approx.ftz.f32 %0,%1;" : "=f"(e) : "f"(s));
            const u64 e2 = pack2(e, e);
            acc[i][0] = fma2(e2, vA.x, acc[i][0]);
            acc[i][1] = fma2(e2, vA.y, acc[i][1]);
            acc[i][2] = fma2(e2, vB.x, acc[i][2]);
            acc[i][3] = fma2(e2, vB.y, acc[i][3]);
        }
    }

    #pragma unroll
    for (int i = 0; i < QBLOCK; i++) {
        int q = qbase + i * ATHREADS;
        u64* pp = reinterpret_cast<u64*>(g_part) + (((size_t)ch * NH + nh) * LEN + q) * 4;
        ulonglong2 o0; o0.x = acc[i][0]; o0.y = acc[i][1];
        ulonglong2 o1; o1.x = acc[i][2]; o1.y = acc[i][3];
        *reinterpret_cast<ulonglong2*>(pp)     = o0;
        *reinterpret_cast<ulonglong2*>(pp + 2) = o1;
    }
}

// ---------------------------------------------------------------------------
// Kernel 3: combine partials + normalize. 4 rows/thread, all float4 I/O.
// ---------------------------------------------------------------------------
__global__ void combine_kernel(float* __restrict__ out)
{
    const int r0 = (blockIdx.x * 256 + threadIdx.x) * 4;   // 4 rows of 131072
    const float4* p0 = reinterpret_cast<const float4*>(g_part + (size_t)r0 * 8);
    const float4* p1 = reinterpret_cast<const float4*>(g_part + (size_t)NH * LEN * 8 + (size_t)r0 * 8);

    float buf[28];
    #pragma unroll
    for (int r = 0; r < 4; r++) {
        float4 A = p0[r * 2], B = p0[r * 2 + 1];
        float4 C = p1[r * 2], D = p1[r * 2 + 1];
        float inv = 1.0f / (B.w + D.w);
        float* o = buf + r * 7;
        o[0] = (A.x + C.x) * inv;
        o[1] = (A.y + C.y) * inv;
        o[2] = (A.z + C.z) * inv;
        o[3] = (A.w + C.w) * inv;
        o[4] = (B.x + D.x) * inv;
        o[5] = (B.y + D.y) * inv;
        o[6] = (B.z + D.z) * inv;
    }
    float4* op = reinterpret_cast<float4*>(out + (size_t)r0 * 7);  // 112B aligned
    #pragma unroll
    for (int i = 0; i < 7; i++)
        op[i] = *reinterpret_cast<float4*>(buf + i * 4);
}

// ---------------------------------------------------------------------------
extern "C" void kernel_launch(void* const* d_in, const int* in_sizes, int n_in,
                              void* d_out, int out_size)
{
    const float* x  = (const float*)d_in[0];
    const float* Wq = (const float*)d_in[1];
    const float* bq = (const float*)d_in[2];
    const float* Wk = (const float*)d_in[3];
    const float* bk = (const float*)d_in[4];
    const float* Wv = (const float*)d_in[5];
    const float* bv = (const float*)d_in[6];
    float* out = (float*)d_out;

    cudaFuncSetAttribute(proj_kernel, cudaFuncAttributeMaxDynamicSharedMemorySize, PROJ_SMEM);
    cudaFuncSetAttribute(attn_kernel, cudaFuncAttributeMaxDynamicSharedMemorySize, ATTN_SMEM);

    prep_kernel<<<(3 * 56 * SZ + 255) / 256, 256>>>(Wq, Wk, Wv);

    dim3 pgrid((NB * LEN) / PROJ_ROWS, 3);       // 256 x 3
    proj_kernel<<<pgrid, PTHREADS, PROJ_SMEM>>>(x, bq, bk, bv);

    dim3 agrid(NH, LEN / QPC, 2);                // 128 x 4 x 2
    attn_kernel<<<agrid, ATHREADS, ATTN_SMEM>>>();

    combine_kernel<<<NH * LEN / 4 / 256, 256>>>(out);
}

// round 4
// speedup vs baseline: 1.5048x; 1.0963x over previous
#include <cuda_runtime.h>
#include <cstdint>

#define NB   8
#define CH   16
#define LEN  1024
#define DD   7
#define SZ   112
#define HH   16
#define NH   (NB*HH)      // 128
#define DPAD 8

typedef unsigned long long u64;

// Scratch
__device__ float g_q[NH * LEN * DPAD];
__device__ float g_k[NH * LEN * DPAD];
__device__ float g_v[NH * LEN * DPAD];
__device__ float g_part[2 * NH * LEN * DPAD];   // [chunk][nh][l][8]
__device__ u64   g_w2[3 * 56 * SZ];             // packed W: [m][k2][j]

// ---- f32x2 helpers ----
__device__ __forceinline__ u64 pack2(float lo, float hi) {
    u64 r; asm("mov.b64 %0,{%1,%2};" : "=l"(r) : "f"(lo), "f"(hi)); return r;
}
__device__ __forceinline__ void unpack2(u64 v, float& lo, float& hi) {
    asm("mov.b64 {%0,%1},%2;" : "=f"(lo), "=f"(hi) : "l"(v));
}
__device__ __forceinline__ u64 fma2(u64 a, u64 b, u64 c) {
    u64 d; asm("fma.rn.f32x2 %0,%1,%2,%3;" : "=l"(d) : "l"(a), "l"(b), "l"(c)); return d;
}
__device__ __forceinline__ u64 mul2(u64 a, u64 b) {
    u64 d; asm("mul.rn.f32x2 %0,%1,%2;" : "=l"(d) : "l"(a), "l"(b)); return d;
}

// ---------------------------------------------------------------------------
// Kernel 0: pack W into [k2][j] u64 table
// ---------------------------------------------------------------------------
__global__ void prep_kernel(const float* __restrict__ Wq,
                            const float* __restrict__ Wk,
                            const float* __restrict__ Wv)
{
    int i = blockIdx.x * 256 + threadIdx.x;
    if (i >= 3 * 56 * SZ) return;
    int m   = i / (56 * SZ);
    int rem = i - m * 56 * SZ;
    int k2  = rem / SZ;
    int j   = rem - k2 * SZ;
    const float* W = (m == 0) ? Wq : (m == 1) ? Wk : Wv;
    g_w2[i] = *reinterpret_cast<const u64*>(W + j * SZ + 2 * k2);
}

// ---------------------------------------------------------------------------
// Kernel 1: QKV projection (k-packed f32x2)
// ---------------------------------------------------------------------------
#define PROJ_ROWS 32
#define PTHREADS  224
#define PROJ_SMEM (56 * SZ * 8 + PROJ_ROWS * SZ * 4)

__global__ __launch_bounds__(PTHREADS, 3)
void proj_kernel(const float* __restrict__ x,
                 const float* __restrict__ bq,
                 const float* __restrict__ bk,
                 const float* __restrict__ bv)
{
    extern __shared__ char smraw[];
    u64*   Wt2 = reinterpret_cast<u64*>(smraw);                  // [56][112]
    float* xs  = reinterpret_cast<float*>(smraw + 56 * SZ * 8);  // [32][112]

    const int m = blockIdx.y;
    const float* b = (m == 0) ? bq : (m == 1) ? bk : bv;
    float* dst     = (m == 0) ? g_q : (m == 1) ? g_k : g_v;

    const int t = threadIdx.x;

    const u64* wsrc = g_w2 + m * 56 * SZ;
    #pragma unroll
    for (int i = 0; i < 28; i++) Wt2[i * PTHREADS + t] = wsrc[i * PTHREADS + t];

    const int base = blockIdx.x * PROJ_ROWS;
    #pragma unroll
    for (int it = 0; it < 16; it++) {
        int i = it * PTHREADS + t;
        int r = i / SZ, c = i - r * SZ;
        int row = base + r;
        int n = row >> 10, l = row & 1023;
        xs[r * SZ + c] = x[((n * CH + c / DD) * LEN + l) * DD + (c % DD)];
    }
    __syncthreads();

    const int jt = t % 28, rt = t / 28;
    const int j0 = jt * 4, r0 = rt * 4;

    u64 acc[4][4];
    #pragma unroll
    for (int rr = 0; rr < 4; rr++)
        #pragma unroll
        for (int jj = 0; jj < 4; jj++) acc[rr][jj] = 0ull;

    #pragma unroll 4
    for (int k2 = 0; k2 < 56; k2++) {
        ulonglong2 wA = *reinterpret_cast<const ulonglong2*>(Wt2 + k2 * SZ + j0);
        ulonglong2 wB = *reinterpret_cast<const ulonglong2*>(Wt2 + k2 * SZ + j0 + 2);
        #pragma unroll
        for (int rr = 0; rr < 4; rr++) {
            u64 xv = *reinterpret_cast<const u64*>(xs + (r0 + rr) * SZ + 2 * k2);
            acc[rr][0] = fma2(xv, wA.x, acc[rr][0]);
            acc[rr][1] = fma2(xv, wA.y, acc[rr][1]);
            acc[rr][2] = fma2(xv, wB.x, acc[rr][2]);
            acc[rr][3] = fma2(xv, wB.y, acc[rr][3]);
        }
    }

    #pragma unroll
    for (int rr = 0; rr < 4; rr++) {
        int row = base + r0 + rr;
        int n = row >> 10, l = row & 1023;
        #pragma unroll
        for (int jj = 0; jj < 4; jj++) {
            int j = j0 + jj;
            float lo, hi; unpack2(acc[rr][jj], lo, hi);
            float y = lo + hi + b[j];
            int h = j / DD, dd = j - h * DD;
            dst[((n * HH + h) * LEN + l) * DPAD + dd] = y;
        }
    }
}

// ---------------------------------------------------------------------------
// Kernel 2: attention partials, KEY-PAIR packed layout.
// smem kt/vt: [j2][16] floats where [j2][d*2+p] = K[2*j2+p][d].
// QK: 7 fma2 -> both scores, no horizontal add. PV: parity-split accs.
// 64 threads x QBLOCK=2 queries; KCH=512 keys (J2=256 pairs); 2 k-chunks.
// ---------------------------------------------------------------------------
#define ATHREADS 64
#define QBLOCK   2
#define QPC      (ATHREADS * QBLOCK)    // 128 queries per CTA
#define KCH      512
#define J2       (KCH / 2)              // 256
#define ATTN_SMEM (2 * J2 * 16 * 4)     // 32768

__global__ __launch_bounds__(ATHREADS, 7)
void attn_kernel()
{
    extern __shared__ float sm[];
    float* kt = sm;                 // [256][16]
    float* vt = sm + J2 * 16;       // [256][16]

    const int nh = blockIdx.x;
    const int ch = blockIdx.z;
    const int t  = threadIdx.x;

    // Stage K/V transposed into key-pair layout.
    {
        const float4* ksrc = reinterpret_cast<const float4*>(g_k + (nh * LEN + ch * KCH) * DPAD);
        const float4* vsrc = reinterpret_cast<const float4*>(g_v + (nh * LEN + ch * KCH) * DPAD);
        #pragma unroll
        for (int it = 0; it < (KCH * 2) / ATHREADS; it++) {
            int i = it * ATHREADS + t;        // float4 index: j*2 + h
            int j = i >> 1, h = i & 1;
            int j2 = j >> 1, p = j & 1;
            float4 kv = ksrc[i];
            float4 vv = vsrc[i];
            float* dk = kt + j2 * 16 + h * 8 + p;
            dk[0] = kv.x; dk[2] = kv.y; dk[4] = kv.z; dk[6] = kv.w;
            float* dv = vt + j2 * 16 + h * 8 + p;
            dv[0] = vv.x; dv[2] = vv.y; dv[4] = vv.z; dv[6] = vv.w;
        }
    }
    __syncthreads();
    // vt lane d=7 (offsets 14,15) carries ssum (v == 1.0); kt d=7 unused.
    for (int j2 = t; j2 < J2; j2 += ATHREADS) {
        vt[j2 * 16 + 14] = 1.0f;
        vt[j2 * 16 + 15] = 1.0f;
        kt[j2 * 16 + 14] = 0.0f;
        kt[j2 * 16 + 15] = 0.0f;
    }
    __syncthreads();

    const int qbase = blockIdx.y * QPC + t;
    const float SC = 1.4426950408889634f / 32.0f;   // log2(e)/sqrt(L)

    u64 qd[QBLOCK][7];        // broadcast pairs {q[d],q[d]} * SC
    u64 accP[QBLOCK][8];      // parity-split accumulators (7 dims + ssum)
    #pragma unroll
    for (int i = 0; i < QBLOCK; i++) {
        const float* qp = g_q + (nh * LEN + qbase + i * ATHREADS) * DPAD;
        #pragma unroll
        for (int d = 0; d < 7; d++) {
            float v = qp[d] * SC;
            qd[i][d] = pack2(v, v);
        }
        #pragma unroll
        for (int d = 0; d < 8; d++) accP[i][d] = 0ull;
    }

    #pragma unroll 2
    for (int j2 = 0; j2 < J2; j2++) {
        const float* kr = kt + j2 * 16;
        const float* vr = vt + j2 * 16;
        const ulonglong2 kA = *reinterpret_cast<const ulonglong2*>(kr);      // d0,d1
        const ulonglong2 kB = *reinterpret_cast<const ulonglong2*>(kr + 4);  // d2,d3
        const ulonglong2 kC = *reinterpret_cast<const ulonglong2*>(kr + 8);  // d4,d5
        const ulonglong2 kD = *reinterpret_cast<const ulonglong2*>(kr + 12); // d6,(pad)
        const ulonglong2 vA = *reinterpret_cast<const ulonglong2*>(vr);
        const ulonglong2 vB = *reinterpret_cast<const ulonglong2*>(vr + 4);
        const ulonglong2 vC = *reinterpret_cast<const ulonglong2*>(vr + 8);
        const ulonglong2 vD = *reinterpret_cast<const ulonglong2*>(vr + 12); // d6, ones
        #pragma unroll
        for (int i = 0; i < QBLOCK; i++) {
            u64 s2 = mul2(qd[i][0], kA.x);
            s2 = fma2(qd[i][1], kA.y, s2);
            s2 = fma2(qd[i][2], kB.x, s2);
            s2 = fma2(qd[i][3], kB.y, s2);
            s2 = fma2(qd[i][4], kC.x, s2);
            s2 = fma2(qd[i][5], kC.y, s2);
            s2 = fma2(qd[i][6], kD.x, s2);
            float s0, s1; unpack2(s2, s0, s1);
            float e0, e1;
            asm("ex2.approx.ftz.f32 %0,%1;" : "=f"(e0) : "f"(s0));
            asm("ex2.approx.ftz.f32 %0,%1;" : "=f"(e1) : "f"(s1));
            const u64 e2 = pack2(e0, e1);
            accP[i][0] = fma2(e2, vA.x, accP[i][0]);
            accP[i][1] = fma2(e2, vA.y, accP[i][1]);
            accP[i][2] = fma2(e2, vB.x, accP[i][2]);
            accP[i][3] = fma2(e2, vB.y, accP[i][3]);
            accP[i][4] = fma2(e2, vC.x, accP[i][4]);
            accP[i][5] = fma2(e2, vC.y, accP[i][5]);
            accP[i][6] = fma2(e2, vD.x, accP[i][6]);
            accP[i][7] = fma2(e2, vD.y, accP[i][7]);   // ssum
        }
    }

    #pragma unroll
    for (int i = 0; i < QBLOCK; i++) {
        int q = qbase + i * ATHREADS;
        float buf[8];
        #pragma unroll
        for (int d = 0; d < 8; d++) {
            float lo, hi; unpack2(accP[i][d], lo, hi);
            buf[d] = lo + hi;
        }
        float4* pp = reinterpret_cast<float4*>(g_part + (((size_t)ch * NH + nh) * LEN + q) * 8);
        pp[0] = make_float4(buf[0], buf[1], buf[2], buf[3]);
        pp[1] = make_float4(buf[4], buf[5], buf[6], buf[7]);
    }
}

// ---------------------------------------------------------------------------
// Kernel 3: combine partials + normalize. 1 row/thread, 512 CTAs.
// ---------------------------------------------------------------------------
__global__ void combine_kernel(float* __restrict__ out)
{
    int idx = blockIdx.x * 256 + threadIdx.x;      // over NH*LEN = 131072
    const float4* p0 = reinterpret_cast<const float4*>(g_part + (size_t)idx * 8);
    const float4* p1 = reinterpret_cast<const float4*>(g_part + (size_t)NH * LEN * 8 + (size_t)idx * 8);
    float4 A = p0[0], B = p0[1];
    float4 C = p1[0], D = p1[1];
    float inv = 1.0f / (B.w + D.w);
    float* op = out + (size_t)idx * DD;
    op[0] = (A.x + C.x) * inv;
    op[1] = (A.y + C.y) * inv;
    op[2] = (A.z + C.z) * inv;
    op[3] = (A.w + C.w) * inv;
    op[4] = (B.x + D.x) * inv;
    op[5] = (B.y + D.y) * inv;
    op[6] = (B.z + D.z) * inv;
}

// ---------------------------------------------------------------------------
extern "C" void kernel_launch(void* const* d_in, const int* in_sizes, int n_in,
                              void* d_out, int out_size)
{
    const float* x  = (const float*)d_in[0];
    const float* Wq = (const float*)d_in[1];
    const float* bq = (const float*)d_in[2];
    const float* Wk = (const float*)d_in[3];
    const float* bk = (const float*)d_in[4];
    const float* Wv = (const float*)d_in[5];
    const float* bv = (const float*)d_in[6];
    float* out = (float*)d_out;

    cudaFuncSetAttribute(proj_kernel, cudaFuncAttributeMaxDynamicSharedMemorySize, PROJ_SMEM);
    cudaFuncSetAttribute(attn_kernel, cudaFuncAttributeMaxDynamicSharedMemorySize, ATTN_SMEM);

    prep_kernel<<<(3 * 56 * SZ + 255) / 256, 256>>>(Wq, Wk, Wv);

    dim3 pgrid((NB * LEN) / PROJ_ROWS, 3);       // 256 x 3
    proj_kernel<<<pgrid, PTHREADS, PROJ_SMEM>>>(x, bq, bk, bv);

    dim3 agrid(NH, LEN / QPC, 2);                // 128 x 8 x 2
    attn_kernel<<<agrid, ATHREADS, ATTN_SMEM>>>();

    combine_kernel<<<NH * LEN / 256, 256>>>(out);
}